// round 8
// baseline (speedup 1.0000x reference)
#include <cuda_runtime.h>
#include <cuda_bf16.h>
#include <cstdint>

// ---------------- problem constants ----------------
#define BB   8
#define NT   2
#define NN   2000
#define ENN  4000
#define NNZE 32000
#define LL   8
#define DD   64
#define LD   512
#define SEG  (BB*NT)
#define NPB  8             // nodes per block -> M = 64
#define NBLK (NN/NPB)      // 250
#define KD   192

// A smem: 64 rows x 200 bf16 slots (400 B/row, 192 used). hi then lo.
#define AROW 200
#define A_BYTES (64 * AROW * 2)      // 25600
#define SMEM_TOTAL (2 * A_BYTES)     // 51200

#define NTASK (BB * NN * NT)         // 32000 gather tasks

// ---------------- device scratch ----------------
__device__ int   g_count [SEG * NN];
__device__ int   g_cursor[SEG * NN];
__device__ int   g_rowptr[SEG * (NN + 1)];
__device__ int2  g_e     [SEG * NNZE];   // packed {val bits, col}
// W images: [mat(3)][n(64)][k(192)] bf16, hi and lo
__device__ __align__(16) __nv_bfloat16 g_Wb_hi[3 * 64 * 192];
__device__ __align__(16) __nv_bfloat16 g_Wb_lo[3 * 64 * 192];
// SpMM staging: [B*NN*8 rows][128 cols] bf16 (cols: 0..64 a_in, 64..128 a_out)
__device__ __align__(16) __nv_bfloat16 g_Shi[(size_t)BB * NN * 8 * 128];
__device__ __align__(16) __nv_bfloat16 g_Slo[(size_t)BB * NN * 8 * 128];

// ---------------- helpers ----------------
__device__ __forceinline__ uint32_t smem_u32(const void* p) {
    uint32_t a;
    asm("{ .reg .u64 t; cvta.to.shared.u64 t, %1; cvt.u32.u64 %0, t; }" : "=r"(a) : "l"(p));
    return a;
}
__device__ __forceinline__ float sigm(float x) { return 1.0f / (1.0f + __expf(-x)); }

#define LDMATRIX_X4(r0, r1, r2, r3, addr) \
    asm volatile("ldmatrix.sync.aligned.m8n8.x4.shared.b16 {%0,%1,%2,%3}, [%4];" \
        : "=r"(r0), "=r"(r1), "=r"(r2), "=r"(r3) : "r"(addr))

#define MMA16816(c, a0, a1, a2, a3, b0, b1) \
    asm volatile("mma.sync.aligned.m16n8k16.row.col.f32.bf16.bf16.f32 " \
        "{%0,%1,%2,%3}, {%4,%5,%6,%7}, {%8,%9}, {%0,%1,%2,%3};" \
        : "+f"((c)[0]), "+f"((c)[1]), "+f"((c)[2]), "+f"((c)[3]) \
        : "r"(a0), "r"(a1), "r"(a2), "r"(a3), "r"(b0), "r"(b1))

// ---------------- init: zero counts + W prep (fused) ----------------
__global__ void k_init(const float* __restrict__ Wr,
                       const float* __restrict__ Wz,
                       const float* __restrict__ Wh) {
    int idx = blockIdx.x * blockDim.x + threadIdx.x;
    if (idx < SEG * NN) g_count[idx] = 0;
    if (idx < 3 * 64 * 192) {
        int mat = idx / (64 * 192);
        int r   = idx - mat * (64 * 192);
        const float* W = (mat == 0) ? Wr : (mat == 1) ? Wz : Wh;
        float w = W[r];
        __nv_bfloat16 hi = __float2bfloat16(w);
        __nv_bfloat16 lo = __float2bfloat16(w - __bfloat162float(hi));
        g_Wb_hi[idx] = hi;
        g_Wb_lo[idx] = lo;
    }
}

__global__ void k_hist(const int* __restrict__ rows) {
    int idx = blockIdx.x * blockDim.x + threadIdx.x;
    if (idx >= SEG * NNZE) return;
    int seg = idx / NNZE;
    atomicAdd(&g_count[seg * NN + rows[idx]], 1);
}
__global__ void k_scan() {
    int seg = blockIdx.x;
    int t   = threadIdx.x;
    __shared__ int sm2[256];
    int c[8];
    int ts = 0;
    int base = seg * NN;
#pragma unroll
    for (int j = 0; j < 8; ++j) {
        int idx = t * 8 + j;
        c[j] = (idx < NN) ? g_count[base + idx] : 0;
        ts += c[j];
    }
    sm2[t] = ts;
    __syncthreads();
    for (int off = 1; off < 256; off <<= 1) {
        int v = sm2[t];
        if (t >= off) v += sm2[t - off];
        __syncthreads();
        sm2[t] = v;
        __syncthreads();
    }
    int run = sm2[t] - ts;
#pragma unroll
    for (int j = 0; j < 8; ++j) {
        int idx = t * 8 + j;
        if (idx < NN) {
            g_rowptr[seg * (NN + 1) + idx] = run;
            g_cursor[base + idx] = run;
            run += c[j];
        }
    }
    if (t == 255) g_rowptr[seg * (NN + 1) + NN] = sm2[255];
}
__global__ void k_scatter(const float* __restrict__ vals,
                          const int*   __restrict__ rows,
                          const int*   __restrict__ cols) {
    int idx = blockIdx.x * blockDim.x + threadIdx.x;
    if (idx >= SEG * NNZE) return;
    int seg = idx / NNZE;
    int pos = atomicAdd(&g_cursor[seg * NN + rows[idx]], 1);
    g_e[seg * NNZE + pos] = make_int2(__float_as_int(vals[idx]), cols[idx]);
}

// ---------------- standalone high-occupancy SpMM gather ----------------
// One warp per (b, n, type) task. Writes bf16 hi/lo messages to staging.
__global__ void __launch_bounds__(256)
k_gather(const float* __restrict__ state_in,
         const float* __restrict__ state_out) {
    const int gw   = (blockIdx.x * blockDim.x + threadIdx.x) >> 5;
    const int lane = threadIdx.x & 31;
    if (gw >= NTASK) return;

    const int type = gw & 1;
    const int R    = gw >> 1;            // global node row: b*NN + n
    const int b    = R / NN;
    const int n    = R - b * NN;
    const int seg  = b * NT + type;

    const int start = g_rowptr[seg * (NN + 1) + n];
    const int end   = g_rowptr[seg * (NN + 1) + n + 1];
    const float* S  = (type == 0 ? state_in : state_out) + (size_t)b * ENN * LD;
    const int2*  E  = g_e + seg * NNZE;
    const int    rem = end - start;

    float4 a0 = {0,0,0,0}, a1 = {0,0,0,0}, a2 = {0,0,0,0}, a3 = {0,0,0,0};

    if (rem > 0) {
        int2 e0 = __ldg(&E[start]);
        int2 e1 = __ldg(&E[start + ((rem > 1) ? 1 : 0)]);
        const float4* r0p = reinterpret_cast<const float4*>(S + (size_t)e0.y * LD);
        const float4* r1p = reinterpret_cast<const float4*>(S + (size_t)e1.y * LD);
        float4 p00 = __ldg(r0p + lane);
        float4 p01 = __ldg(r0p + 32 + lane);
        float4 p02 = __ldg(r0p + 64 + lane);
        float4 p03 = __ldg(r0p + 96 + lane);
        float4 p10 = __ldg(r1p + lane);
        float4 p11 = __ldg(r1p + 32 + lane);
        float4 p12 = __ldg(r1p + 64 + lane);
        float4 p13 = __ldg(r1p + 96 + lane);

        int i = 0;
        while (i + 2 <= rem) {
            const int i2 = (i + 2 < rem) ? (i + 2) : (rem - 1);
            const int i3 = (i + 3 < rem) ? (i + 3) : (rem - 1);
            int2 f0 = __ldg(&E[start + i2]);
            int2 f1 = __ldg(&E[start + i3]);

            const float va = __int_as_float(e0.x);
            const float vb = __int_as_float(e1.x);

            a0.x += va * p00.x; a0.y += va * p00.y; a0.z += va * p00.z; a0.w += va * p00.w;
            a1.x += va * p01.x; a1.y += va * p01.y; a1.z += va * p01.z; a1.w += va * p01.w;
            a2.x += va * p02.x; a2.y += va * p02.y; a2.z += va * p02.z; a2.w += va * p02.w;
            a3.x += va * p03.x; a3.y += va * p03.y; a3.z += va * p03.z; a3.w += va * p03.w;
            a0.x += vb * p10.x; a0.y += vb * p10.y; a0.z += vb * p10.z; a0.w += vb * p10.w;
            a1.x += vb * p11.x; a1.y += vb * p11.y; a1.z += vb * p11.z; a1.w += vb * p11.w;
            a2.x += vb * p12.x; a2.y += vb * p12.y; a2.z += vb * p12.z; a2.w += vb * p12.w;
            a3.x += vb * p13.x; a3.y += vb * p13.y; a3.z += vb * p13.z; a3.w += vb * p13.w;

            const float4* q0p = reinterpret_cast<const float4*>(S + (size_t)f0.y * LD);
            const float4* q1p = reinterpret_cast<const float4*>(S + (size_t)f1.y * LD);
            p00 = __ldg(q0p + lane);
            p01 = __ldg(q0p + 32 + lane);
            p02 = __ldg(q0p + 64 + lane);
            p03 = __ldg(q0p + 96 + lane);
            p10 = __ldg(q1p + lane);
            p11 = __ldg(q1p + 32 + lane);
            p12 = __ldg(q1p + 64 + lane);
            p13 = __ldg(q1p + 96 + lane);

            e0 = f0; e1 = f1;
            i += 2;
        }
        if (i < rem) {
            const float va = __int_as_float(e0.x);
            a0.x += va * p00.x; a0.y += va * p00.y; a0.z += va * p00.z; a0.w += va * p00.w;
            a1.x += va * p01.x; a1.y += va * p01.y; a1.z += va * p01.z; a1.w += va * p01.w;
            a2.x += va * p02.x; a2.y += va * p02.y; a2.z += va * p02.z; a2.w += va * p02.w;
            a3.x += va * p03.x; a3.y += va * p03.y; a3.z += va * p03.z; a3.w += va * p03.w;
        }
    }

    float4 acc[4] = {a0, a1, a2, a3};
#pragma unroll
    for (int j = 0; j < 4; ++j) {
        const int Eidx = j * 32 + lane;
        const int l    = Eidx >> 4;
        const int d4   = (Eidx & 15) * 4;
        float4 vx = acc[j];
        __nv_bfloat162 h01 = __floats2bfloat162_rn(vx.x, vx.y);
        __nv_bfloat162 h23 = __floats2bfloat162_rn(vx.z, vx.w);
        __nv_bfloat162 l01 = __floats2bfloat162_rn(vx.x - __bfloat162float(h01.x),
                                                   vx.y - __bfloat162float(h01.y));
        __nv_bfloat162 l23 = __floats2bfloat162_rn(vx.z - __bfloat162float(h23.x),
                                                   vx.w - __bfloat162float(h23.y));
        uint2 hw, lw;
        hw.x = *reinterpret_cast<uint32_t*>(&h01);
        hw.y = *reinterpret_cast<uint32_t*>(&h23);
        lw.x = *reinterpret_cast<uint32_t*>(&l01);
        lw.y = *reinterpret_cast<uint32_t*>(&l23);
        const size_t off = ((size_t)R * 8 + l) * 128 + type * DD + d4;
        *reinterpret_cast<uint2*>(&g_Shi[off]) = hw;
        *reinterpret_cast<uint2*>(&g_Slo[off]) = lw;
    }
}

// ---------------- GEMM + GRU kernel ----------------
__global__ void __launch_bounds__(256)
k_gemm(const float* __restrict__ state_cur,
       const float* __restrict__ b_r,
       const float* __restrict__ b_z,
       const float* __restrict__ b_h,
       float* __restrict__ out) {
    extern __shared__ char smem[];
    __nv_bfloat16* Ah = reinterpret_cast<__nv_bfloat16*>(smem);
    __nv_bfloat16* Al = reinterpret_cast<__nv_bfloat16*>(smem + A_BYTES);
    const uint32_t sbh = smem_u32(smem);
    const uint32_t sbl = sbh + A_BYTES;

    const int tid  = threadIdx.x;
    const int w    = tid >> 5;
    const int lane = tid & 31;
    const int b    = blockIdx.x / NBLK;
    const int nb   = (blockIdx.x - b * NBLK) * NPB;

    // ---------- Phase 1a: copy staged a_in|a_out tiles into smem ----------
    {
        const size_t Rbase = (size_t)(b * NN + nb) * 8;   // 64 staging rows
        const uint4* Hs = reinterpret_cast<const uint4*>(g_Shi) + Rbase * 16;
        const uint4* Ls = reinterpret_cast<const uint4*>(g_Slo) + Rbase * 16;
#pragma unroll
        for (int rep = 0; rep < 4; ++rep) {
            const int i = tid + rep * 256;   // [0,1024): r = i>>4, c = i&15 (uint4 within 128 cols)
            const int r = i >> 4;
            const int c = i & 15;
            uint4 vh = __ldg(&Hs[i]);
            uint4 vl = __ldg(&Ls[i]);
            *reinterpret_cast<uint4*>(&Ah[r * AROW + c * 8]) = vh;
            *reinterpret_cast<uint4*>(&Al[r * AROW + c * 8]) = vl;
        }
    }
    // ---------- Phase 1b: state_cur -> bf16 hi/lo cols 128..192 ----------
    {
        const float4* C4 = reinterpret_cast<const float4*>(state_cur + (size_t)(b * NN + nb) * LD);
#pragma unroll
        for (int rep = 0; rep < 4; ++rep) {
            const int F    = tid + rep * 256;   // float4 index [0,1024)
            const int node = F >> 7;
            const int l    = (F >> 4) & 7;
            const int d4   = (F & 15) * 4;
            float4 vx = __ldg(C4 + F);
            const int row = node * LL + l;
            const int kb  = 128 + d4;
            __nv_bfloat162 h01 = __floats2bfloat162_rn(vx.x, vx.y);
            __nv_bfloat162 h23 = __floats2bfloat162_rn(vx.z, vx.w);
            __nv_bfloat162 l01 = __floats2bfloat162_rn(vx.x - __bfloat162float(h01.x),
                                                       vx.y - __bfloat162float(h01.y));
            __nv_bfloat162 l23 = __floats2bfloat162_rn(vx.z - __bfloat162float(h23.x),
                                                       vx.w - __bfloat162float(h23.y));
            uint2 hw, lw;
            hw.x = *reinterpret_cast<uint32_t*>(&h01);
            hw.y = *reinterpret_cast<uint32_t*>(&h23);
            lw.x = *reinterpret_cast<uint32_t*>(&l01);
            lw.y = *reinterpret_cast<uint32_t*>(&l23);
            *reinterpret_cast<uint2*>(&Ah[row * AROW + kb]) = hw;
            *reinterpret_cast<uint2*>(&Al[row * AROW + kb]) = lw;
        }
    }
    __syncthreads();

    // ---------- Phase 2: HMMA GEMMs ----------
    const int n0 = w * 8;
    const int qr = lane >> 2;
    const int qc = (lane & 3) * 2;

    float cr[16], cz[16], ch[16];
#pragma unroll
    for (int i = 0; i < 16; ++i) { cr[i] = 0.0f; cz[i] = 0.0f; ch[i] = 0.0f; }

    const int arow = lane & 15;
    const int koff16 = ((lane >> 4) & 1) * 16;
    const int bnr = (n0 + qr) * 192 + qc;

#pragma unroll
    for (int kt = 0; kt < 8; ++kt) {
        const int k0 = kt * 16;
        const uint32_t brh0 = *reinterpret_cast<const uint32_t*>(g_Wb_hi + bnr + k0);
        const uint32_t brh1 = *reinterpret_cast<const uint32_t*>(g_Wb_hi + bnr + k0 + 8);
        const uint32_t brl0 = *reinterpret_cast<const uint32_t*>(g_Wb_lo + bnr + k0);
        const uint32_t brl1 = *reinterpret_cast<const uint32_t*>(g_Wb_lo + bnr + k0 + 8);
        const uint32_t bzh0 = *reinterpret_cast<const uint32_t*>(g_Wb_hi + 64*192 + bnr + k0);
        const uint32_t bzh1 = *reinterpret_cast<const uint32_t*>(g_Wb_hi + 64*192 + bnr + k0 + 8);
        const uint32_t bzl0 = *reinterpret_cast<const uint32_t*>(g_Wb_lo + 64*192 + bnr + k0);
        const uint32_t bzl1 = *reinterpret_cast<const uint32_t*>(g_Wb_lo + 64*192 + bnr + k0 + 8);
        const uint32_t bhh0 = *reinterpret_cast<const uint32_t*>(g_Wb_hi + 128*192 + bnr + k0);
        const uint32_t bhh1 = *reinterpret_cast<const uint32_t*>(g_Wb_hi + 128*192 + bnr + k0 + 8);
        const uint32_t bhl0 = *reinterpret_cast<const uint32_t*>(g_Wb_lo + 128*192 + bnr + k0);
        const uint32_t bhl1 = *reinterpret_cast<const uint32_t*>(g_Wb_lo + 128*192 + bnr + k0 + 8);
#pragma unroll
        for (int i = 0; i < 4; ++i) {
            const uint32_t aoff = (uint32_t)((16 * i + arow) * 400 + k0 * 2 + koff16);
            uint32_t ah0, ah1, ah2, ah3, al0, al1, al2, al3;
            LDMATRIX_X4(ah0, ah1, ah2, ah3, sbh + aoff);
            LDMATRIX_X4(al0, al1, al2, al3, sbl + aoff);
            MMA16816(cr + 4*i, ah0, ah1, ah2, ah3, brh0, brh1);
            MMA16816(cr + 4*i, al0, al1, al2, al3, brh0, brh1);
            MMA16816(cr + 4*i, ah0, ah1, ah2, ah3, brl0, brl1);
            MMA16816(cz + 4*i, ah0, ah1, ah2, ah3, bzh0, bzh1);
            MMA16816(cz + 4*i, al0, al1, al2, al3, bzh0, bzh1);
            MMA16816(cz + 4*i, ah0, ah1, ah2, ah3, bzl0, bzl1);
            MMA16816(ch + 4*i, ah0, ah1, ah2, ah3, bhh0, bhh1);
            MMA16816(ch + 4*i, al0, al1, al2, al3, bhh0, bhh1);
            MMA16816(ch + 4*i, ah0, ah1, ah2, ah3, bhl0, bhl1);
        }
    }
#pragma unroll
    for (int kt = 8; kt < 12; ++kt) {
        const int k0 = kt * 16;
        const uint32_t brh0 = *reinterpret_cast<const uint32_t*>(g_Wb_hi + bnr + k0);
        const uint32_t brh1 = *reinterpret_cast<const uint32_t*>(g_Wb_hi + bnr + k0 + 8);
        const uint32_t brl0 = *reinterpret_cast<const uint32_t*>(g_Wb_lo + bnr + k0);
        const uint32_t brl1 = *reinterpret_cast<const uint32_t*>(g_Wb_lo + bnr + k0 + 8);
        const uint32_t bzh0 = *reinterpret_cast<const uint32_t*>(g_Wb_hi + 64*192 + bnr + k0);
        const uint32_t bzh1 = *reinterpret_cast<const uint32_t*>(g_Wb_hi + 64*192 + bnr + k0 + 8);
        const uint32_t bzl0 = *reinterpret_cast<const uint32_t*>(g_Wb_lo + 64*192 + bnr + k0);
        const uint32_t bzl1 = *reinterpret_cast<const uint32_t*>(g_Wb_lo + 64*192 + bnr + k0 + 8);
#pragma unroll
        for (int i = 0; i < 4; ++i) {
            const uint32_t aoff = (uint32_t)((16 * i + arow) * 400 + k0 * 2 + koff16);
            uint32_t ah0, ah1, ah2, ah3, al0, al1, al2, al3;
            LDMATRIX_X4(ah0, ah1, ah2, ah3, sbh + aoff);
            LDMATRIX_X4(al0, al1, al2, al3, sbl + aoff);
            MMA16816(cr + 4*i, ah0, ah1, ah2, ah3, brh0, brh1);
            MMA16816(cr + 4*i, al0, al1, al2, al3, brh0, brh1);
            MMA16816(cr + 4*i, ah0, ah1, ah2, ah3, brl0, brl1);
            MMA16816(cz + 4*i, ah0, ah1, ah2, ah3, bzh0, bzh1);
            MMA16816(cz + 4*i, al0, al1, al2, al3, bzh0, bzh1);
            MMA16816(cz + 4*i, ah0, ah1, ah2, ah3, bzl0, bzl1);
        }
    }
    __syncthreads();

    // ---------- Epilogue 1: r, z; write rc = r*cur over cur columns ----------
    float curv[16], zreg[16];
#pragma unroll
    for (int i = 0; i < 4; ++i) {
#pragma unroll
        for (int rr = 0; rr < 2; ++rr) {
            const int m = 16 * i + qr + 8 * rr;
#pragma unroll
            for (int cc = 0; cc < 2; ++cc) {
                const int o   = n0 + qc + cc;
                const int idx = i * 4 + rr * 2 + cc;
                const int e   = m * AROW + 128 + o;
                const float cur = __bfloat162float(Ah[e]) + __bfloat162float(Al[e]);
                curv[idx] = cur;
                const float rv = sigm(cr[idx] + __ldg(&b_r[o]));
                zreg[idx] = sigm(cz[idx] + __ldg(&b_z[o]));
                const float rc = rv * cur;
                const __nv_bfloat16 hi = __float2bfloat16(rc);
                Ah[e] = hi;
                Al[e] = __float2bfloat16(rc - __bfloat162float(hi));
            }
        }
    }
    __syncthreads();

    // ---------- Phase 3: finish h with rc columns ----------
#pragma unroll
    for (int kt = 8; kt < 12; ++kt) {
        const int k0 = kt * 16;
        const uint32_t bhh0 = *reinterpret_cast<const uint32_t*>(g_Wb_hi + 128*192 + bnr + k0);
        const uint32_t bhh1 = *reinterpret_cast<const uint32_t*>(g_Wb_hi + 128*192 + bnr + k0 + 8);
        const uint32_t bhl0 = *reinterpret_cast<const uint32_t*>(g_Wb_lo + 128*192 + bnr + k0);
        const uint32_t bhl1 = *reinterpret_cast<const uint32_t*>(g_Wb_lo + 128*192 + bnr + k0 + 8);
#pragma unroll
        for (int i = 0; i < 4; ++i) {
            const uint32_t aoff = (uint32_t)((16 * i + arow) * 400 + k0 * 2 + koff16);
            uint32_t ah0, ah1, ah2, ah3, al0, al1, al2, al3;
            LDMATRIX_X4(ah0, ah1, ah2, ah3, sbh + aoff);
            LDMATRIX_X4(al0, al1, al2, al3, sbl + aoff);
            MMA16816(ch + 4*i, ah0, ah1, ah2, ah3, bhh0, bhh1);
            MMA16816(ch + 4*i, al0, al1, al2, al3, bhh0, bhh1);
            MMA16816(ch + 4*i, ah0, ah1, ah2, ah3, bhl0, bhl1);
        }
    }

    // ---------- Epilogue 2: GRU combine + store ----------
#pragma unroll
    for (int i = 0; i < 4; ++i) {
#pragma unroll
        for (int rr = 0; rr < 2; ++rr) {
            const int m    = 16 * i + qr + 8 * rr;
            const int node = m >> 3;
            const int l    = m & 7;
            const size_t grow = ((size_t)(b * NN + nb + node) * LL + l);
            float2 v;
#pragma unroll
            for (int cc = 0; cc < 2; ++cc) {
                const int o   = n0 + qc + cc;
                const int idx = i * 4 + rr * 2 + cc;
                const float h = tanhf(ch[idx] + __ldg(&b_h[o]));
                const float z = zreg[idx];
                const float r2 = (1.0f - z) * curv[idx] + z * h;
                if (cc == 0) v.x = r2; else v.y = r2;
            }
            *reinterpret_cast<float2*>(out + grow * DD + n0 + qc) = v;
        }
    }
}

// ---------------- launch ----------------
extern "C" void kernel_launch(void* const* d_in, const int* in_sizes, int n_in,
                              void* d_out, int out_size) {
    (void)in_sizes; (void)n_in; (void)out_size;
    const float* state_in  = (const float*)d_in[0];
    const float* state_out = (const float*)d_in[1];
    const float* state_cur = (const float*)d_in[2];
    const float* A_vals    = (const float*)d_in[3];
    const int*   A_rows    = (const int*)  d_in[4];
    const int*   A_cols    = (const int*)  d_in[5];
    const float* W_r       = (const float*)d_in[6];
    const float* b_r       = (const float*)d_in[7];
    const float* W_z       = (const float*)d_in[8];
    const float* b_z       = (const float*)d_in[9];
    const float* W_h       = (const float*)d_in[10];
    const float* b_h       = (const float*)d_in[11];
    float* out = (float*)d_out;

    cudaFuncSetAttribute(k_gemm, cudaFuncAttributeMaxDynamicSharedMemorySize, SMEM_TOTAL);

    k_init<<<(3 * 64 * 192 + 255) / 256, 256>>>(W_r, W_z, W_h);
    k_hist<<<(SEG * NNZE + 255) / 256, 256>>>(A_rows);
    k_scan<<<SEG, 256>>>();
    k_scatter<<<(SEG * NNZE + 255) / 256, 256>>>(A_vals, A_rows, A_cols);
    k_gather<<<(NTASK * 32 + 255) / 256, 256>>>(state_in, state_out);
    k_gemm<<<BB * NBLK, 256, SMEM_TOTAL>>>(state_cur, b_r, b_z, b_h, out);
}

// round 9
// speedup vs baseline: 1.1367x; 1.1367x over previous
#include <cuda_runtime.h>
#include <cuda_bf16.h>
#include <cstdint>

// ---------------- problem constants ----------------
#define BB   8
#define NT   2
#define NN   2000
#define ENN  4000
#define NNZE 32000
#define LL   8
#define DD   64
#define LD   512
#define SEG  (BB*NT)
#define NPB  8             // nodes per block -> M = 64
#define NBLK (NN/NPB)      // 250
#define KD   192
#define BCAP 128           // bucket capacity per (seg,row); Poisson(16) => overflow ~impossible

// A smem: 64 rows x 200 bf16 slots (400 B/row, 192 used). hi then lo.
#define AROW 200
#define A_BYTES (64 * AROW * 2)      // 25600
#define SMEM_TOTAL (2 * A_BYTES)     // 51200

// ---------------- device scratch ----------------
__device__ int   g_cnt [SEG * NN];
__device__ int2  g_bkt [(size_t)SEG * NN * BCAP];   // packed {val bits, col}
// W images: [mat(3)][n(64)][k(192)] bf16, hi and lo
__device__ __align__(16) __nv_bfloat16 g_Wb_hi[3 * 64 * 192];
__device__ __align__(16) __nv_bfloat16 g_Wb_lo[3 * 64 * 192];

// ---------------- helpers ----------------
__device__ __forceinline__ uint32_t smem_u32(const void* p) {
    uint32_t a;
    asm("{ .reg .u64 t; cvta.to.shared.u64 t, %1; cvt.u32.u64 %0, t; }" : "=r"(a) : "l"(p));
    return a;
}
__device__ __forceinline__ float sigm(float x) { return 1.0f / (1.0f + __expf(-x)); }

#define LDMATRIX_X4(r0, r1, r2, r3, addr) \
    asm volatile("ldmatrix.sync.aligned.m8n8.x4.shared.b16 {%0,%1,%2,%3}, [%4];" \
        : "=r"(r0), "=r"(r1), "=r"(r2), "=r"(r3) : "r"(addr))

#define MMA16816(c, a0, a1, a2, a3, b0, b1) \
    asm volatile("mma.sync.aligned.m16n8k16.row.col.f32.bf16.bf16.f32 " \
        "{%0,%1,%2,%3}, {%4,%5,%6,%7}, {%8,%9}, {%0,%1,%2,%3};" \
        : "+f"((c)[0]), "+f"((c)[1]), "+f"((c)[2]), "+f"((c)[3]) \
        : "r"(a0), "r"(a1), "r"(a2), "r"(a3), "r"(b0), "r"(b1))

// ---------------- init: zero counts + W prep (fused) ----------------
__global__ void k_init(const float* __restrict__ Wr,
                       const float* __restrict__ Wz,
                       const float* __restrict__ Wh) {
    int idx = blockIdx.x * blockDim.x + threadIdx.x;
    if (idx < SEG * NN) g_cnt[idx] = 0;
    if (idx < 3 * 64 * 192) {
        int mat = idx / (64 * 192);
        int r   = idx - mat * (64 * 192);
        const float* W = (mat == 0) ? Wr : (mat == 1) ? Wz : Wh;
        float w = W[r];
        __nv_bfloat16 hi = __float2bfloat16(w);
        __nv_bfloat16 lo = __float2bfloat16(w - __bfloat162float(hi));
        g_Wb_hi[idx] = hi;
        g_Wb_lo[idx] = lo;
    }
}

// ---------------- single-pass bucketed edge build ----------------
__global__ void k_scatter(const float* __restrict__ vals,
                          const int*   __restrict__ rows,
                          const int*   __restrict__ cols) {
    int idx = blockIdx.x * blockDim.x + threadIdx.x;
    if (idx >= SEG * NNZE) return;
    int seg = idx / NNZE;
    int slot = seg * NN + rows[idx];
    int pos = atomicAdd(&g_cnt[slot], 1);
    if (pos < BCAP)
        g_bkt[(size_t)slot * BCAP + pos] = make_int2(__float_as_int(vals[idx]), cols[idx]);
}

// ---------------- main fused kernel (R7-proven structure) ----------------
__global__ void __launch_bounds__(256)
k_main(const float* __restrict__ state_in,
       const float* __restrict__ state_out,
       const float* __restrict__ state_cur,
       const float* __restrict__ b_r,
       const float* __restrict__ b_z,
       const float* __restrict__ b_h,
       float* __restrict__ out) {
    extern __shared__ char smem[];
    __nv_bfloat16* Ah = reinterpret_cast<__nv_bfloat16*>(smem);
    __nv_bfloat16* Al = reinterpret_cast<__nv_bfloat16*>(smem + A_BYTES);
    const uint32_t sbh = smem_u32(smem);
    const uint32_t sbl = sbh + A_BYTES;

    const int tid  = threadIdx.x;
    const int w    = tid >> 5;
    const int lane = tid & 31;
    const int b    = blockIdx.x / NBLK;
    const int nb   = (blockIdx.x - b * NBLK) * NPB;

    // ---------- Phase 1: SpMM gather (pipelined row loads, dist-2 prefetch) ----------
    for (int task = w; task < 16; task += 8) {
        const int node = task >> 1;
        const int type = task & 1;
        const int n    = nb + node;
        const int seg  = b * NT + type;
        const int slot = seg * NN + n;
        const float* S  = (type == 0 ? state_in : state_out) + (size_t)b * ENN * LD;
        const int2*  E  = g_bkt + (size_t)slot * BCAP;
        int rem = g_cnt[slot];
        if (rem > BCAP) rem = BCAP;

        float4 a0 = {0,0,0,0}, a1 = {0,0,0,0}, a2 = {0,0,0,0}, a3 = {0,0,0,0};

        if (rem > 0) {
            int2 e0 = __ldg(&E[0]);
            int2 e1 = __ldg(&E[(rem > 1) ? 1 : 0]);
            const float4* r0p = reinterpret_cast<const float4*>(S + (size_t)e0.y * LD);
            const float4* r1p = reinterpret_cast<const float4*>(S + (size_t)e1.y * LD);
            float4 p00 = __ldg(r0p + lane);
            float4 p01 = __ldg(r0p + 32 + lane);
            float4 p02 = __ldg(r0p + 64 + lane);
            float4 p03 = __ldg(r0p + 96 + lane);
            float4 p10 = __ldg(r1p + lane);
            float4 p11 = __ldg(r1p + 32 + lane);
            float4 p12 = __ldg(r1p + 64 + lane);
            float4 p13 = __ldg(r1p + 96 + lane);

            int i = 0;
            while (i + 2 <= rem) {
                const int i2 = (i + 2 < rem) ? (i + 2) : (rem - 1);
                const int i3 = (i + 3 < rem) ? (i + 3) : (rem - 1);
                int2 f0 = __ldg(&E[i2]);
                int2 f1 = __ldg(&E[i3]);

                const float va = __int_as_float(e0.x);
                const float vb = __int_as_float(e1.x);

                a0.x += va * p00.x; a0.y += va * p00.y; a0.z += va * p00.z; a0.w += va * p00.w;
                a1.x += va * p01.x; a1.y += va * p01.y; a1.z += va * p01.z; a1.w += va * p01.w;
                a2.x += va * p02.x; a2.y += va * p02.y; a2.z += va * p02.z; a2.w += va * p02.w;
                a3.x += va * p03.x; a3.y += va * p03.y; a3.z += va * p03.z; a3.w += va * p03.w;
                a0.x += vb * p10.x; a0.y += vb * p10.y; a0.z += vb * p10.z; a0.w += vb * p10.w;
                a1.x += vb * p11.x; a1.y += vb * p11.y; a1.z += vb * p11.z; a1.w += vb * p11.w;
                a2.x += vb * p12.x; a2.y += vb * p12.y; a2.z += vb * p12.z; a2.w += vb * p12.w;
                a3.x += vb * p13.x; a3.y += vb * p13.y; a3.z += vb * p13.z; a3.w += vb * p13.w;

                const float4* q0p = reinterpret_cast<const float4*>(S + (size_t)f0.y * LD);
                const float4* q1p = reinterpret_cast<const float4*>(S + (size_t)f1.y * LD);
                p00 = __ldg(q0p + lane);
                p01 = __ldg(q0p + 32 + lane);
                p02 = __ldg(q0p + 64 + lane);
                p03 = __ldg(q0p + 96 + lane);
                p10 = __ldg(q1p + lane);
                p11 = __ldg(q1p + 32 + lane);
                p12 = __ldg(q1p + 64 + lane);
                p13 = __ldg(q1p + 96 + lane);

                e0 = f0; e1 = f1;
                i += 2;
            }
            if (i < rem) {
                const float va = __int_as_float(e0.x);
                a0.x += va * p00.x; a0.y += va * p00.y; a0.z += va * p00.z; a0.w += va * p00.w;
                a1.x += va * p01.x; a1.y += va * p01.y; a1.z += va * p01.z; a1.w += va * p01.w;
                a2.x += va * p02.x; a2.y += va * p02.y; a2.z += va * p02.z; a2.w += va * p02.w;
                a3.x += va * p03.x; a3.y += va * p03.y; a3.z += va * p03.z; a3.w += va * p03.w;
            }
        }

        float4 acc[4] = {a0, a1, a2, a3};
#pragma unroll
        for (int j = 0; j < 4; ++j) {
            const int Eidx = j * 32 + lane;
            const int l    = Eidx >> 4;
            const int d4   = (Eidx & 15) * 4;
            const int row  = node * LL + l;
            const int kb   = type * DD + d4;
            float4 vx = acc[j];
            __nv_bfloat162 h01 = __floats2bfloat162_rn(vx.x, vx.y);
            __nv_bfloat162 h23 = __floats2bfloat162_rn(vx.z, vx.w);
            __nv_bfloat162 l01 = __floats2bfloat162_rn(vx.x - __bfloat162float(h01.x),
                                                       vx.y - __bfloat162float(h01.y));
            __nv_bfloat162 l23 = __floats2bfloat162_rn(vx.z - __bfloat162float(h23.x),
                                                       vx.w - __bfloat162float(h23.y));
            uint2 hw, lw;
            hw.x = *reinterpret_cast<uint32_t*>(&h01);
            hw.y = *reinterpret_cast<uint32_t*>(&h23);
            lw.x = *reinterpret_cast<uint32_t*>(&l01);
            lw.y = *reinterpret_cast<uint32_t*>(&l23);
            *reinterpret_cast<uint2*>(&Ah[row * AROW + kb]) = hw;
            *reinterpret_cast<uint2*>(&Al[row * AROW + kb]) = lw;
        }
    }
    // state_cur: warp w loads node w
    {
        const int n = nb + w;
        const float4* C = reinterpret_cast<const float4*>(state_cur + (size_t)(b * NN + n) * LD);
#pragma unroll
        for (int j = 0; j < 4; ++j) {
            const int Eidx = j * 32 + lane;
            const int l    = Eidx >> 4;
            const int d4   = (Eidx & 15) * 4;
            float4 vx = __ldg(C + Eidx);
            const int row = w * LL + l;
            const int kb  = 128 + d4;
            __nv_bfloat162 h01 = __floats2bfloat162_rn(vx.x, vx.y);
            __nv_bfloat162 h23 = __floats2bfloat162_rn(vx.z, vx.w);
            __nv_bfloat162 l01 = __floats2bfloat162_rn(vx.x - __bfloat162float(h01.x),
                                                       vx.y - __bfloat162float(h01.y));
            __nv_bfloat162 l23 = __floats2bfloat162_rn(vx.z - __bfloat162float(h23.x),
                                                       vx.w - __bfloat162float(h23.y));
            uint2 hw, lw;
            hw.x = *reinterpret_cast<uint32_t*>(&h01);
            hw.y = *reinterpret_cast<uint32_t*>(&h23);
            lw.x = *reinterpret_cast<uint32_t*>(&l01);
            lw.y = *reinterpret_cast<uint32_t*>(&l23);
            *reinterpret_cast<uint2*>(&Ah[row * AROW + kb]) = hw;
            *reinterpret_cast<uint2*>(&Al[row * AROW + kb]) = lw;
        }
    }
    __syncthreads();

    // ---------- Phase 2: HMMA GEMMs ----------
    const int n0 = w * 8;
    const int qr = lane >> 2;
    const int qc = (lane & 3) * 2;

    float cr[16], cz[16], ch[16];
#pragma unroll
    for (int i = 0; i < 16; ++i) { cr[i] = 0.0f; cz[i] = 0.0f; ch[i] = 0.0f; }

    const int arow = lane & 15;
    const int koff16 = ((lane >> 4) & 1) * 16;
    const int bnr = (n0 + qr) * 192 + qc;

#pragma unroll
    for (int kt = 0; kt < 8; ++kt) {
        const int k0 = kt * 16;
        const uint32_t brh0 = *reinterpret_cast<const uint32_t*>(g_Wb_hi + bnr + k0);
        const uint32_t brh1 = *reinterpret_cast<const uint32_t*>(g_Wb_hi + bnr + k0 + 8);
        const uint32_t brl0 = *reinterpret_cast<const uint32_t*>(g_Wb_lo + bnr + k0);
        const uint32_t brl1 = *reinterpret_cast<const uint32_t*>(g_Wb_lo + bnr + k0 + 8);
        const uint32_t bzh0 = *reinterpret_cast<const uint32_t*>(g_Wb_hi + 64*192 + bnr + k0);
        const uint32_t bzh1 = *reinterpret_cast<const uint32_t*>(g_Wb_hi + 64*192 + bnr + k0 + 8);
        const uint32_t bzl0 = *reinterpret_cast<const uint32_t*>(g_Wb_lo + 64*192 + bnr + k0);
        const uint32_t bzl1 = *reinterpret_cast<const uint32_t*>(g_Wb_lo + 64*192 + bnr + k0 + 8);
        const uint32_t bhh0 = *reinterpret_cast<const uint32_t*>(g_Wb_hi + 128*192 + bnr + k0);
        const uint32_t bhh1 = *reinterpret_cast<const uint32_t*>(g_Wb_hi + 128*192 + bnr + k0 + 8);
        const uint32_t bhl0 = *reinterpret_cast<const uint32_t*>(g_Wb_lo + 128*192 + bnr + k0);
        const uint32_t bhl1 = *reinterpret_cast<const uint32_t*>(g_Wb_lo + 128*192 + bnr + k0 + 8);
#pragma unroll
        for (int i = 0; i < 4; ++i) {
            const uint32_t aoff = (uint32_t)((16 * i + arow) * 400 + k0 * 2 + koff16);
            uint32_t ah0, ah1, ah2, ah3, al0, al1, al2, al3;
            LDMATRIX_X4(ah0, ah1, ah2, ah3, sbh + aoff);
            LDMATRIX_X4(al0, al1, al2, al3, sbl + aoff);
            MMA16816(cr + 4*i, ah0, ah1, ah2, ah3, brh0, brh1);
            MMA16816(cr + 4*i, al0, al1, al2, al3, brh0, brh1);
            MMA16816(cr + 4*i, ah0, ah1, ah2, ah3, brl0, brl1);
            MMA16816(cz + 4*i, ah0, ah1, ah2, ah3, bzh0, bzh1);
            MMA16816(cz + 4*i, al0, al1, al2, al3, bzh0, bzh1);
            MMA16816(cz + 4*i, ah0, ah1, ah2, ah3, bzl0, bzl1);
            MMA16816(ch + 4*i, ah0, ah1, ah2, ah3, bhh0, bhh1);
            MMA16816(ch + 4*i, al0, al1, al2, al3, bhh0, bhh1);
            MMA16816(ch + 4*i, ah0, ah1, ah2, ah3, bhl0, bhl1);
        }
    }
#pragma unroll
    for (int kt = 8; kt < 12; ++kt) {
        const int k0 = kt * 16;
        const uint32_t brh0 = *reinterpret_cast<const uint32_t*>(g_Wb_hi + bnr + k0);
        const uint32_t brh1 = *reinterpret_cast<const uint32_t*>(g_Wb_hi + bnr + k0 + 8);
        const uint32_t brl0 = *reinterpret_cast<const uint32_t*>(g_Wb_lo + bnr + k0);
        const uint32_t brl1 = *reinterpret_cast<const uint32_t*>(g_Wb_lo + bnr + k0 + 8);
        const uint32_t bzh0 = *reinterpret_cast<const uint32_t*>(g_Wb_hi + 64*192 + bnr + k0);
        const uint32_t bzh1 = *reinterpret_cast<const uint32_t*>(g_Wb_hi + 64*192 + bnr + k0 + 8);
        const uint32_t bzl0 = *reinterpret_cast<const uint32_t*>(g_Wb_lo + 64*192 + bnr + k0);
        const uint32_t bzl1 = *reinterpret_cast<const uint32_t*>(g_Wb_lo + 64*192 + bnr + k0 + 8);
#pragma unroll
        for (int i = 0; i < 4; ++i) {
            const uint32_t aoff = (uint32_t)((16 * i + arow) * 400 + k0 * 2 + koff16);
            uint32_t ah0, ah1, ah2, ah3, al0, al1, al2, al3;
            LDMATRIX_X4(ah0, ah1, ah2, ah3, sbh + aoff);
            LDMATRIX_X4(al0, al1, al2, al3, sbl + aoff);
            MMA16816(cr + 4*i, ah0, ah1, ah2, ah3, brh0, brh1);
            MMA16816(cr + 4*i, al0, al1, al2, al3, brh0, brh1);
            MMA16816(cr + 4*i, ah0, ah1, ah2, ah3, brl0, brl1);
            MMA16816(cz + 4*i, ah0, ah1, ah2, ah3, bzh0, bzh1);
            MMA16816(cz + 4*i, al0, al1, al2, al3, bzh0, bzh1);
            MMA16816(cz + 4*i, ah0, ah1, ah2, ah3, bzl0, bzl1);
        }
    }
    __syncthreads();

    // ---------- Epilogue 1: r, z; write rc = r*cur over cur columns ----------
    float curv[16], zreg[16];
#pragma unroll
    for (int i = 0; i < 4; ++i) {
#pragma unroll
        for (int rr = 0; rr < 2; ++rr) {
            const int m = 16 * i + qr + 8 * rr;
#pragma unroll
            for (int cc = 0; cc < 2; ++cc) {
                const int o   = n0 + qc + cc;
                const int idx = i * 4 + rr * 2 + cc;
                const int e   = m * AROW + 128 + o;
                const float cur = __bfloat162float(Ah[e]) + __bfloat162float(Al[e]);
                curv[idx] = cur;
                const float rv = sigm(cr[idx] + __ldg(&b_r[o]));
                zreg[idx] = sigm(cz[idx] + __ldg(&b_z[o]));
                const float rc = rv * cur;
                const __nv_bfloat16 hi = __float2bfloat16(rc);
                Ah[e] = hi;
                Al[e] = __float2bfloat16(rc - __bfloat162float(hi));
            }
        }
    }
    __syncthreads();

    // ---------- Phase 3: finish h with rc columns ----------
#pragma unroll
    for (int kt = 8; kt < 12; ++kt) {
        const int k0 = kt * 16;
        const uint32_t bhh0 = *reinterpret_cast<const uint32_t*>(g_Wb_hi + 128*192 + bnr + k0);
        const uint32_t bhh1 = *reinterpret_cast<const uint32_t*>(g_Wb_hi + 128*192 + bnr + k0 + 8);
        const uint32_t bhl0 = *reinterpret_cast<const uint32_t*>(g_Wb_lo + 128*192 + bnr + k0);
        const uint32_t bhl1 = *reinterpret_cast<const uint32_t*>(g_Wb_lo + 128*192 + bnr + k0 + 8);
#pragma unroll
        for (int i = 0; i < 4; ++i) {
            const uint32_t aoff = (uint32_t)((16 * i + arow) * 400 + k0 * 2 + koff16);
            uint32_t ah0, ah1, ah2, ah3, al0, al1, al2, al3;
            LDMATRIX_X4(ah0, ah1, ah2, ah3, sbh + aoff);
            LDMATRIX_X4(al0, al1, al2, al3, sbl + aoff);
            MMA16816(ch + 4*i, ah0, ah1, ah2, ah3, bhh0, bhh1);
            MMA16816(ch + 4*i, al0, al1, al2, al3, bhh0, bhh1);
            MMA16816(ch + 4*i, ah0, ah1, ah2, ah3, bhl0, bhl1);
        }
    }

    // ---------- Epilogue 2: GRU combine + store ----------
#pragma unroll
    for (int i = 0; i < 4; ++i) {
#pragma unroll
        for (int rr = 0; rr < 2; ++rr) {
            const int m    = 16 * i + qr + 8 * rr;
            const int node = m >> 3;
            const int l    = m & 7;
            const size_t grow = ((size_t)(b * NN + nb + node) * LL + l);
            float2 v;
#pragma unroll
            for (int cc = 0; cc < 2; ++cc) {
                const int o   = n0 + qc + cc;
                const int idx = i * 4 + rr * 2 + cc;
                const float h = tanhf(ch[idx] + __ldg(&b_h[o]));
                const float z = zreg[idx];
                const float r2 = (1.0f - z) * curv[idx] + z * h;
                if (cc == 0) v.x = r2; else v.y = r2;
            }
            *reinterpret_cast<float2*>(out + grow * DD + n0 + qc) = v;
        }
    }
}

// ---------------- launch ----------------
extern "C" void kernel_launch(void* const* d_in, const int* in_sizes, int n_in,
                              void* d_out, int out_size) {
    (void)in_sizes; (void)n_in; (void)out_size;
    const float* state_in  = (const float*)d_in[0];
    const float* state_out = (const float*)d_in[1];
    const float* state_cur = (const float*)d_in[2];
    const float* A_vals    = (const float*)d_in[3];
    const int*   A_rows    = (const int*)  d_in[4];
    const int*   A_cols    = (const int*)  d_in[5];
    const float* W_r       = (const float*)d_in[6];
    const float* b_r       = (const float*)d_in[7];
    const float* W_z       = (const float*)d_in[8];
    const float* b_z       = (const float*)d_in[9];
    const float* W_h       = (const float*)d_in[10];
    const float* b_h       = (const float*)d_in[11];
    float* out = (float*)d_out;

    cudaFuncSetAttribute(k_main, cudaFuncAttributeMaxDynamicSharedMemorySize, SMEM_TOTAL);

    k_init<<<(3 * 64 * 192 + 255) / 256, 256>>>(W_r, W_z, W_h);
    k_scatter<<<(SEG * NNZE + 255) / 256, 256>>>(A_vals, A_rows, A_cols);
    k_main<<<BB * NBLK, 256, SMEM_TOTAL>>>(state_in, state_out, state_cur,
                                           b_r, b_z, b_h, out);
}